// round 3
// baseline (speedup 1.0000x reference)
#include <cuda_runtime.h>
#include <cstdint>
#include <cstddef>

#define N_NODES 50000
#define N_EDGES 800000
#define DIN     128
#define HC      128
#define ED      32

// ---------------- scratch (device globals; no allocations allowed) ----------
__device__ __align__(16) float g_Q[N_NODES * HC];
__device__ __align__(16) float g_K[N_NODES * HC];
__device__ __align__(16) float g_V[N_NODES * HC];
__device__ __align__(16) float g_QW[N_NODES * 64];      // [N][H=2][32] = q @ We_h^T
__device__ __align__(16) float g_Wqe[DIN * 64];         // combined Wq@We_h^T  [128][64]
__device__ __align__(16) float g_bqW[64];

// sort scratch
__device__ int  g_hist[N_NODES];
__device__ int  g_off[N_NODES];
__device__ int  g_cursor[N_NODES];
__device__ int  g_bsum[256];
__device__ int  g_bpre[256];
__device__ __align__(8) int2 g_sorted2[N_EDGES];        // (src, edge_id) sorted by dst

// ---------------- f32x2 helpers (Blackwell packed fp32) ---------------------
typedef unsigned long long u64;
__device__ __forceinline__ u64 pack2(float a, float b) {
    u64 r; asm("mov.b64 %0, {%1, %2};" : "=l"(r) : "f"(a), "f"(b)); return r;
}
__device__ __forceinline__ void unpack2(u64 v, float& a, float& b) {
    asm("mov.b64 {%0, %1}, %2;" : "=f"(a), "=f"(b) : "l"(v));
}
__device__ __forceinline__ u64 fma2(u64 a, u64 b, u64 c) {
    u64 d; asm("fma.rn.f32x2 %0, %1, %2, %3;" : "=l"(d) : "l"(a), "l"(b), "l"(c)); return d;
}

// ---------------- zero hist --------------------------------------------------
__global__ void zero_hist() {
    int i = blockIdx.x * 256 + threadIdx.x;
    if (i < N_NODES) g_hist[i] = 0;
}

// ---------------- combined weight Wqe = fold(We into Wq), bias too ----------
__global__ void combine_we(const float* __restrict__ Wq, const float* __restrict__ bq,
                           const float* __restrict__ We) {
    int g = blockIdx.x * 256 + threadIdx.x;
    if (g < DIN * 64) {
        int r = g >> 6, o = g & 63;
        int h = o >> 5, d = o & 31, base = h * 64;
        float s = 0.0f;
        for (int c = 0; c < 64; c++)
            s += Wq[r * HC + base + c] * We[d * HC + base + c];
        g_Wqe[r * 64 + o] = s;
    } else if (g < DIN * 64 + 64) {
        int o = g - DIN * 64;
        int h = o >> 5, d = o & 31, base = h * 64;
        float s = 0.0f;
        for (int c = 0; c < 64; c++)
            s += bq[base + c] * We[d * HC + base + c];
        g_bqW[o] = s;
    }
}

// ---------------- node GEMM, K-pair-packed FFMA2 ----------------------------
// Tile: 128 rows x 64 cols. blockIdx.y in 0..8:
//   0,1 -> Q cols [0,64),[64,128)   2,3 -> K   4,5 -> V   6,7 -> skip(out)
//   8   -> qW (B=g_Wqe, 64 cols)
// Accumulators are f32x2 pairs over (even k, odd k); final result = lo + hi.
__global__ __launch_bounds__(256, 2)
void gemm128(const float* __restrict__ A,
             const float* __restrict__ Wq, const float* __restrict__ bq,
             const float* __restrict__ Wk, const float* __restrict__ bk,
             const float* __restrict__ Wv, const float* __restrict__ bv,
             const float* __restrict__ Ws, const float* __restrict__ bs,
             float* __restrict__ outp, int M) {
    __shared__ u64 As64[16][130];   // [k2][m]  (k-pairs of A), padded
    __shared__ u64 Bs64[16][66];    // [k2][n]  (B[2k][n],B[2k+1][n]) interleaved

    const float* Bsrc; const float* bias; float* D;
    int ldb, ldd, nc0;
    int y = blockIdx.y;
    if (y < 8) {
        int mat = y >> 1;
        nc0 = (y & 1) * 64; ldb = 128; ldd = 128;
        switch (mat) {
            case 0:  Bsrc = Wq; bias = bq; D = g_Q;  break;
            case 1:  Bsrc = Wk; bias = bk; D = g_K;  break;
            case 2:  Bsrc = Wv; bias = bv; D = g_V;  break;
            default: Bsrc = Ws; bias = bs; D = outp; break;
        }
    } else {
        Bsrc = g_Wqe; bias = g_bqW; D = g_QW; ldb = 64; ldd = 64; nc0 = 0;
    }

    int m0 = blockIdx.x * 128;
    int t  = threadIdx.x;
    int tx = t & 15, ty = t >> 4;       // thread -> (4 cols, 8 rows)

    u64 acc[8][4];
#pragma unroll
    for (int r = 0; r < 8; r++)
#pragma unroll
        for (int c = 0; c < 4; c++) acc[r][c] = 0ULL;

    int ldb4 = ldb >> 2;

    for (int kk = 0; kk < 4; kk++) {
        // stage A: rows m0..+127, k chunk [kk*32, +32), as k-pairs
#pragma unroll
        for (int i = 0; i < 4; i++) {
            int idx = i * 256 + t;          // 0..1023 float4 slots
            int row = idx >> 3;             // 0..127
            int c4  = idx & 7;              // 0..7
            float4 v = make_float4(0.f, 0.f, 0.f, 0.f);
            if (m0 + row < M)
                v = ((const float4*)A)[(size_t)(m0 + row) * 32 + kk * 8 + c4];
            As64[c4 * 2 + 0][row] = pack2(v.x, v.y);
            As64[c4 * 2 + 1][row] = pack2(v.z, v.w);
        }
        // stage B: rows [kk*32,+32), 64-col slice, interleaved k-pairs
        {
            int k2 = t >> 4;                // 0..15
            int c4 = t & 15;                // 0..15
            const float4* bp4 = (const float4*)Bsrc;
            float4 fa = bp4[(size_t)(kk * 32 + 2 * k2)     * ldb4 + (nc0 >> 2) + c4];
            float4 fb = bp4[(size_t)(kk * 32 + 2 * k2 + 1) * ldb4 + (nc0 >> 2) + c4];
            Bs64[k2][c4 * 4 + 0] = pack2(fa.x, fb.x);
            Bs64[k2][c4 * 4 + 1] = pack2(fa.y, fb.y);
            Bs64[k2][c4 * 4 + 2] = pack2(fa.z, fb.z);
            Bs64[k2][c4 * 4 + 3] = pack2(fa.w, fb.w);
        }
        __syncthreads();
#pragma unroll
        for (int k2 = 0; k2 < 16; k2++) {
            const ulonglong2* ap = (const ulonglong2*)&As64[k2][ty * 8];
            ulonglong2 a01 = ap[0], a23 = ap[1], a45 = ap[2], a67 = ap[3];
            const ulonglong2* bp = (const ulonglong2*)&Bs64[k2][tx * 4];
            ulonglong2 b01 = bp[0], b23 = bp[1];
            u64 av[8] = { a01.x, a01.y, a23.x, a23.y, a45.x, a45.y, a67.x, a67.y };
            u64 bv2[4] = { b01.x, b01.y, b23.x, b23.y };
#pragma unroll
            for (int r = 0; r < 8; r++)
#pragma unroll
                for (int c = 0; c < 4; c++)
                    acc[r][c] = fma2(av[r], bv2[c], acc[r][c]);
        }
        __syncthreads();
    }

    // epilogue: reduce pair halves, add bias, vector store
    float b4[4];
#pragma unroll
    for (int c = 0; c < 4; c++) b4[c] = bias[nc0 + tx * 4 + c];
#pragma unroll
    for (int r = 0; r < 8; r++) {
        int m = m0 + ty * 8 + r;
        if (m >= M) continue;
        float4 o;
        float lo, hi;
        unpack2(acc[r][0], lo, hi); o.x = lo + hi + b4[0];
        unpack2(acc[r][1], lo, hi); o.y = lo + hi + b4[1];
        unpack2(acc[r][2], lo, hi); o.z = lo + hi + b4[2];
        unpack2(acc[r][3], lo, hi); o.w = lo + hi + b4[3];
        *(float4*)&D[(size_t)m * ldd + nc0 + tx * 4] = o;
    }
}

// ---------------- counting sort: histogram, scan, scatter -------------------
__global__ void hist_kernel(const int* __restrict__ ei) {
    int i = blockIdx.x * 256 + threadIdx.x;
    if (i * 4 < N_EDGES) {
        int4 d4 = ((const int4*)(ei + N_EDGES))[i];
        atomicAdd(&g_hist[d4.x], 1);
        atomicAdd(&g_hist[d4.y], 1);
        atomicAdd(&g_hist[d4.z], 1);
        atomicAdd(&g_hist[d4.w], 1);
    }
}

__device__ __forceinline__ int block_exscan(int v, int* sh) {
    int lane = threadIdx.x & 31, w = threadIdx.x >> 5;
    int incl = v;
#pragma unroll
    for (int s = 1; s < 32; s <<= 1) {
        int t = __shfl_up_sync(0xffffffffu, incl, s);
        if (lane >= s) incl += t;
    }
    if (lane == 31) sh[w] = incl;
    __syncthreads();
    if (threadIdx.x == 0) {
        int acc = 0;
#pragma unroll
        for (int i = 0; i < 8; i++) { int t = sh[i]; sh[i] = acc; acc += t; }
    }
    __syncthreads();
    return incl - v + sh[w];
}

__global__ void scan_a() {
    int i = blockIdx.x * 256 + threadIdx.x;
    int v = (i < N_NODES) ? g_hist[i] : 0;
#pragma unroll
    for (int s = 16; s >= 1; s >>= 1) v += __shfl_xor_sync(0xffffffffu, v, s);
    __shared__ int sh[8];
    if ((threadIdx.x & 31) == 0) sh[threadIdx.x >> 5] = v;
    __syncthreads();
    if (threadIdx.x == 0) {
        int s = 0;
#pragma unroll
        for (int j = 0; j < 8; j++) s += sh[j];
        g_bsum[blockIdx.x] = s;
    }
}

__global__ void scan_b(int nblk) {
    __shared__ int sh[8];
    int t = threadIdx.x;
    int v = (t < nblk) ? g_bsum[t] : 0;
    int ex = block_exscan(v, sh);
    if (t < nblk) g_bpre[t] = ex;
}

__global__ void scan_c() {
    __shared__ int sh[8];
    int i = blockIdx.x * 256 + threadIdx.x;
    int v = (i < N_NODES) ? g_hist[i] : 0;
    int ex = block_exscan(v, sh);
    if (i < N_NODES) {
        int off = g_bpre[blockIdx.x] + ex;
        g_off[i] = off;
        g_cursor[i] = off;
    }
}

__global__ void scatter_kernel(const int* __restrict__ ei) {
    int i = blockIdx.x * 256 + threadIdx.x;
    if (i < N_EDGES) {
        int dst = ei[N_EDGES + i];
        int pos = atomicAdd(&g_cursor[dst], 1);
        g_sorted2[pos] = make_int2(ei[i], i);
    }
}

// ---------------- fused per-node attention (warp per node, 2-edge ILP) ------
__global__ __launch_bounds__(256)
void node_fused(const float* __restrict__ ea, const float* __restrict__ We,
                float* __restrict__ out) {
    __shared__ float We_s[32][128];   // 16KB
    __shared__ float eac_s[8][64];
    int t = threadIdx.x;
#pragma unroll
    for (int i = 0; i < 4; i++) {
        int idx = i * 256 + t;        // 1024 float4
        ((float4*)&We_s[0][0])[idx] = ((const float4*)We)[idx];
    }
    __syncthreads();

    int wrp = t >> 5, lane = t & 31;
    int n = blockIdx.x * 8 + wrp;     // 6250 * 8 = 50000 exact
    int half = lane >> 4, l15 = lane & 15;

    float4 q4  = ((const float4*)g_Q)[(size_t)n * 32 + lane];
    float2 qw2 = ((const float2*)g_QW)[(size_t)n * 32 + half * 16 + l15];
    int start = g_off[n];
    int end   = (n == N_NODES - 1) ? N_EDGES : g_off[n + 1];

    float4 vacc = make_float4(0.f, 0.f, 0.f, 0.f);
    float2 eacc = make_float2(0.f, 0.f);
    float denom = 0.f;

    int j = start;
    for (; j + 2 <= end; j += 2) {
        int2 sa = g_sorted2[j];
        int2 sb = g_sorted2[j + 1];
        float4 ka = ((const float4*)g_K)[(size_t)sa.x * 32 + lane];
        float4 kb = ((const float4*)g_K)[(size_t)sb.x * 32 + lane];
        float4 va = ((const float4*)g_V)[(size_t)sa.x * 32 + lane];
        float4 vb = ((const float4*)g_V)[(size_t)sb.x * 32 + lane];
        float2 e2a = ((const float2*)ea)[(size_t)sa.y * 16 + l15];
        float2 e2b = ((const float2*)ea)[(size_t)sb.y * 16 + l15];

        float pa = q4.x * ka.x + q4.y * ka.y + q4.z * ka.z + q4.w * ka.w
                 + e2a.x * qw2.x + e2a.y * qw2.y;
        float pb = q4.x * kb.x + q4.y * kb.y + q4.z * kb.z + q4.w * kb.w
                 + e2b.x * qw2.x + e2b.y * qw2.y;
#pragma unroll
        for (int s = 8; s >= 1; s >>= 1) {
            pa += __shfl_xor_sync(0xffffffffu, pa, s);
            pb += __shfl_xor_sync(0xffffffffu, pb, s);
        }
        float aa = __expf(pa * 0.125f);
        float ab = __expf(pb * 0.125f);
        denom += aa + ab;
        vacc.x += aa * va.x + ab * vb.x;
        vacc.y += aa * va.y + ab * vb.y;
        vacc.z += aa * va.z + ab * vb.z;
        vacc.w += aa * va.w + ab * vb.w;
        eacc.x += aa * e2a.x + ab * e2b.x;
        eacc.y += aa * e2a.y + ab * e2b.y;
    }
    if (j < end) {
        int2 se = g_sorted2[j];
        float4 k4 = ((const float4*)g_K)[(size_t)se.x * 32 + lane];
        float4 v4 = ((const float4*)g_V)[(size_t)se.x * 32 + lane];
        float2 e2 = ((const float2*)ea)[(size_t)se.y * 16 + l15];
        float part = q4.x * k4.x + q4.y * k4.y + q4.z * k4.z + q4.w * k4.w
                   + e2.x * qw2.x + e2.y * qw2.y;
#pragma unroll
        for (int s = 8; s >= 1; s >>= 1) part += __shfl_xor_sync(0xffffffffu, part, s);
        float alpha = __expf(part * 0.125f);
        denom += alpha;
        vacc.x += alpha * v4.x; vacc.y += alpha * v4.y;
        vacc.z += alpha * v4.z; vacc.w += alpha * v4.w;
        eacc.x += alpha * e2.x; eacc.y += alpha * e2.y;
    }

    float inv = 1.0f / (denom + 1e-16f);
    vacc.x *= inv; vacc.y *= inv; vacc.z *= inv; vacc.w *= inv;
    eacc.x *= inv; eacc.y *= inv;

    eac_s[wrp][half * 32 + 2 * l15]     = eacc.x;
    eac_s[wrp][half * 32 + 2 * l15 + 1] = eacc.y;
    __syncwarp();

    int cb = half * 64 + l15 * 4;
    float4 et = make_float4(0.f, 0.f, 0.f, 0.f);
#pragma unroll
    for (int d = 0; d < 32; d++) {
        float ed = eac_s[wrp][half * 32 + d];
        et.x += ed * We_s[d][cb + 0];
        et.y += ed * We_s[d][cb + 1];
        et.z += ed * We_s[d][cb + 2];
        et.w += ed * We_s[d][cb + 3];
    }

    float4 o = ((float4*)out)[(size_t)n * 32 + lane];   // holds skip projection
    o.x += vacc.x + et.x;
    o.y += vacc.y + et.y;
    o.z += vacc.z + et.z;
    o.w += vacc.w + et.w;
    ((float4*)out)[(size_t)n * 32 + lane] = o;
}

// ---------------- launcher ---------------------------------------------------
extern "C" void kernel_launch(void* const* d_in, const int* in_sizes, int n_in,
                              void* d_out, int out_size) {
    const float* x  = (const float*)d_in[0];
    const int*   ei = (const int*)d_in[1];
    const float* ea = (const float*)d_in[2];
    const float* Wq = (const float*)d_in[3];
    const float* bq = (const float*)d_in[4];
    const float* Wk = (const float*)d_in[5];
    const float* bk = (const float*)d_in[6];
    const float* Wv = (const float*)d_in[7];
    const float* bv = (const float*)d_in[8];
    const float* We = (const float*)d_in[9];
    const float* Ws = (const float*)d_in[10];
    const float* bs = (const float*)d_in[11];
    float* out = (float*)d_out;

    const int NB_NODE = (N_NODES + 255) / 256;   // 196
    const int NB_EDGE = (N_EDGES + 255) / 256;   // 3125

    zero_hist<<<NB_NODE, 256>>>();
    combine_we<<<33, 256>>>(Wq, bq, We);

    dim3 gg((N_NODES + 127) / 128, 9);
    gemm128<<<gg, 256>>>(x, Wq, bq, Wk, bk, Wv, bv, Ws, bs, out, N_NODES);

    hist_kernel<<<(N_EDGES / 4 + 255) / 256, 256>>>(ei);
    scan_a<<<NB_NODE, 256>>>();
    scan_b<<<1, 256>>>(NB_NODE);
    scan_c<<<NB_NODE, 256>>>();
    scatter_kernel<<<NB_EDGE, 256>>>(ei);

    node_fused<<<N_NODES / 8, 256>>>(ea, We, out);
}